// round 1
// baseline (speedup 1.0000x reference)
#include <cuda_runtime.h>

#define D 64
#define TQ 64
#define TK 64
#define WINDOW 512
#define S_LEN 4096
#define BH 16
#define NEG_BIG (-1e30f)

__global__ __launch_bounds__(256, 2)
void swa_fwd_kernel(const float* __restrict__ Q,
                    const float* __restrict__ K,
                    const float* __restrict__ V,
                    float* __restrict__ O) {
    __shared__ float ksh[TK][D];
    __shared__ float vsh[TK][D];

    const int bh  = blockIdx.y;
    const int q0  = blockIdx.x * TQ;
    const int t   = threadIdx.x;
    const int qi  = t >> 2;        // query within tile (0..63)
    const int sub = t & 3;         // dim quarter (0..3), 16 dims each
    const int q   = q0 + qi;
    const size_t base = (size_t)bh * S_LEN * D;

    // Load this thread's 16 dims of q, pre-scaled by (1/sqrt(D)) * log2(e)
    // so scores are directly in log2 domain -> exp2f (raw MUFU.EX2).
    const float qscale = 0.125f * 1.44269504088896340736f;
    float4 qr[4];
    {
        const float4* qptr = (const float4*)(Q + base + (size_t)q * D + sub * 16);
        #pragma unroll
        for (int i = 0; i < 4; i++) {
            float4 v4 = qptr[i];
            v4.x *= qscale; v4.y *= qscale; v4.z *= qscale; v4.w *= qscale;
            qr[i] = v4;
        }
    }

    float acc[16];
    #pragma unroll
    for (int i = 0; i < 16; i++) acc[i] = 0.0f;
    float m = NEG_BIG;
    float l = 0.0f;

    // Key-tile range covering the union of all 64 queries' windows.
    const int kt0 = max(0, q0 - (WINDOW - 1)) / TK;
    const int kt1 = blockIdx.x;

    for (int kt = kt0; kt <= kt1; kt++) {
        // Cooperative K/V tile load: 1024 float4 each, 4 per thread, coalesced.
        {
            const float4* kg = (const float4*)(K + base + (size_t)kt * TK * D);
            const float4* vg = (const float4*)(V + base + (size_t)kt * TK * D);
            float4* ks4 = (float4*)&ksh[0][0];
            float4* vs4 = (float4*)&vsh[0][0];
            #pragma unroll
            for (int i = 0; i < 4; i++) {
                ks4[t + 256 * i] = kg[t + 256 * i];
                vs4[t + 256 * i] = vg[t + 256 * i];
            }
        }
        __syncthreads();

        // Scores: each lane does a 16-dim partial dot, group-of-4 shfl reduce.
        // All 4 lanes of a group end up with identical full scores.
        float sc[TK];
        const int jbase = kt * TK;
        #pragma unroll
        for (int j = 0; j < TK; j++) {
            const float4* kr = (const float4*)&ksh[j][sub * 16];
            float s = 0.0f;
            #pragma unroll
            for (int i = 0; i < 4; i++) {
                float4 kv = kr[i];
                s += qr[i].x * kv.x + qr[i].y * kv.y
                   + qr[i].z * kv.z + qr[i].w * kv.w;
            }
            s += __shfl_xor_sync(0xffffffffu, s, 1);
            s += __shfl_xor_sync(0xffffffffu, s, 2);
            const int jg = jbase + j;
            const bool valid = (jg <= q) && (jg >= q - (WINDOW - 1));
            sc[j] = valid ? s : NEG_BIG;
        }

        // Online softmax update (log2 domain).
        float mt = sc[0];
        #pragma unroll
        for (int j = 1; j < TK; j++) mt = fmaxf(mt, sc[j]);
        const float mnew = fmaxf(m, mt);
        const float corr = exp2f(m - mnew);  // flushes to 0 when m==NEG_BIG
        l *= corr;
        #pragma unroll
        for (int i = 0; i < 16; i++) acc[i] *= corr;
        m = mnew;

        #pragma unroll
        for (int j = 0; j < TK; j++) {
            const float p = exp2f(sc[j] - mnew);
            l += p;
            const float4* vr = (const float4*)&vsh[j][sub * 16];
            #pragma unroll
            for (int i = 0; i < 4; i++) {
                float4 vv = vr[i];
                acc[i * 4 + 0] += p * vv.x;
                acc[i * 4 + 1] += p * vv.y;
                acc[i * 4 + 2] += p * vv.z;
                acc[i * 4 + 3] += p * vv.w;
            }
        }
        __syncthreads();
    }

    const float inv = 1.0f / l;
    float4* optr = (float4*)(O + base + (size_t)q * D + sub * 16);
    #pragma unroll
    for (int i = 0; i < 4; i++) {
        float4 o4;
        o4.x = acc[i * 4 + 0] * inv;
        o4.y = acc[i * 4 + 1] * inv;
        o4.z = acc[i * 4 + 2] * inv;
        o4.w = acc[i * 4 + 3] * inv;
        optr[i] = o4;
    }
}

extern "C" void kernel_launch(void* const* d_in, const int* in_sizes, int n_in,
                              void* d_out, int out_size) {
    const float* Q = (const float*)d_in[0];
    const float* K = (const float*)d_in[1];
    const float* V = (const float*)d_in[2];
    float* O = (float*)d_out;
    (void)in_sizes; (void)n_in; (void)out_size;

    dim3 grid(S_LEN / TQ, BH);   // (64, 16) = 1024 blocks
    swa_fwd_kernel<<<grid, 256>>>(Q, K, V, O);
}

// round 2
// speedup vs baseline: 2.6883x; 2.6883x over previous
#include <cuda_runtime.h>

#define D 64
#define TQ 128          // queries per block
#define TK 64           // keys per smem tile
#define WINDOW 512
#define S_LEN 4096
#define BH 16
#define NTHREADS 128

__device__ __forceinline__ float ex2(float x) {
    float y;
    asm("ex2.approx.f32 %0, %1;" : "=f"(y) : "f"(x));
    return y;
}

__global__ __launch_bounds__(NTHREADS, 2)
void swa_fwd_kernel(const float* __restrict__ Q,
                    const float* __restrict__ K,
                    const float* __restrict__ V,
                    float* __restrict__ O) {
    __shared__ float ksh[TK][D];
    __shared__ float vsh[TK][D];

    const int bh   = blockIdx.y;
    const int q0   = blockIdx.x * TQ;
    const int t    = threadIdx.x;
    const int grp  = t >> 2;          // 0..31: group of 4 queries
    const int sub  = t & 3;           // dim quarter (16 floats)
    const int qb   = q0 + grp * 4;    // first of this thread's 4 queries
    const size_t base = (size_t)bh * S_LEN * D;

    // Load 4 queries x 16 dims, pre-scaled by (1/sqrt(D))*log2(e):
    // scores come out directly in log2 domain -> raw EX2.
    const float qscale = 0.125f * 1.44269504088896340736f;
    float4 qr[4][4];
    #pragma unroll
    for (int qq = 0; qq < 4; qq++) {
        const float4* qptr = (const float4*)(Q + base + (size_t)(qb + qq) * D + sub * 16);
        #pragma unroll
        for (int i = 0; i < 4; i++) {
            float4 v4 = qptr[i];
            v4.x *= qscale; v4.y *= qscale; v4.z *= qscale; v4.w *= qscale;
            qr[qq][i] = v4;
        }
    }

    float4 acc[4][4];
    #pragma unroll
    for (int qq = 0; qq < 4; qq++)
        #pragma unroll
        for (int i = 0; i < 4; i++)
            acc[qq][i] = make_float4(0.f, 0.f, 0.f, 0.f);
    float l[4] = {0.f, 0.f, 0.f, 0.f};

    const int kt0 = max(0, q0 - (WINDOW - 1)) / TK;
    const int kt1 = (q0 + TQ - 1) / TK;

    for (int kt = kt0; kt <= kt1; kt++) {
        // Cooperative tile load: 1024 float4 per tensor, 8 per thread, coalesced.
        {
            const float4* kg = (const float4*)(K + base + (size_t)kt * TK * D);
            const float4* vg = (const float4*)(V + base + (size_t)kt * TK * D);
            float4* ks4 = (float4*)&ksh[0][0];
            float4* vs4 = (float4*)&vsh[0][0];
            #pragma unroll
            for (int i = 0; i < 8; i++) {
                ks4[t + NTHREADS * i] = kg[t + NTHREADS * i];
                vs4[t + NTHREADS * i] = vg[t + NTHREADS * i];
            }
        }
        __syncthreads();

        const int jbase = kt * TK;
        #pragma unroll 2
        for (int j = 0; j < TK; j++) {
            // One K-row read (64B), reused by 4 queries.
            const float4* krp = (const float4*)&ksh[j][sub * 16];
            float4 kr[4];
            #pragma unroll
            for (int i = 0; i < 4; i++) kr[i] = krp[i];

            // Partial 16-dim dots for the 4 queries.
            float s[4];
            #pragma unroll
            for (int qq = 0; qq < 4; qq++) {
                float acc_s = qr[qq][0].x * kr[0].x + qr[qq][0].y * kr[0].y
                            + qr[qq][0].z * kr[0].z + qr[qq][0].w * kr[0].w;
                #pragma unroll
                for (int i = 1; i < 4; i++) {
                    acc_s += qr[qq][i].x * kr[i].x + qr[qq][i].y * kr[i].y
                           + qr[qq][i].z * kr[i].z + qr[qq][i].w * kr[i].w;
                }
                s[qq] = acc_s;
            }
            // Reduce across the 4-lane dim group; all 4 lanes get full scores.
            #pragma unroll
            for (int qq = 0; qq < 4; qq++) {
                s[qq] += __shfl_xor_sync(0xffffffffu, s[qq], 1);
                s[qq] += __shfl_xor_sync(0xffffffffu, s[qq], 2);
            }

            const int jg = jbase + j;
            float p[4];
            #pragma unroll
            for (int qq = 0; qq < 4; qq++) {
                const int q = qb + qq;
                const bool valid = (jg <= q) && (jg + (WINDOW - 1) >= q);
                p[qq] = valid ? ex2(s[qq]) : 0.0f;
                l[qq] += p[qq];
            }

            // One V-row read (64B), reused by 4 queries.
            const float4* vrp = (const float4*)&vsh[j][sub * 16];
            float4 vr[4];
            #pragma unroll
            for (int i = 0; i < 4; i++) vr[i] = vrp[i];

            #pragma unroll
            for (int qq = 0; qq < 4; qq++) {
                #pragma unroll
                for (int i = 0; i < 4; i++) {
                    acc[qq][i].x += p[qq] * vr[i].x;
                    acc[qq][i].y += p[qq] * vr[i].y;
                    acc[qq][i].z += p[qq] * vr[i].z;
                    acc[qq][i].w += p[qq] * vr[i].w;
                }
            }
        }
        __syncthreads();
    }

    #pragma unroll
    for (int qq = 0; qq < 4; qq++) {
        const float inv = 1.0f / l[qq];
        float4* optr = (float4*)(O + base + (size_t)(qb + qq) * D + sub * 16);
        #pragma unroll
        for (int i = 0; i < 4; i++) {
            float4 o4;
            o4.x = acc[qq][i].x * inv;
            o4.y = acc[qq][i].y * inv;
            o4.z = acc[qq][i].z * inv;
            o4.w = acc[qq][i].w * inv;
            optr[i] = o4;
        }
    }
}

extern "C" void kernel_launch(void* const* d_in, const int* in_sizes, int n_in,
                              void* d_out, int out_size) {
    const float* Q = (const float*)d_in[0];
    const float* K = (const float*)d_in[1];
    const float* V = (const float*)d_in[2];
    float* O = (float*)d_out;
    (void)in_sizes; (void)n_in; (void)out_size;

    dim3 grid(S_LEN / TQ, BH);   // (32, 16) = 512 blocks
    swa_fwd_kernel<<<grid, NTHREADS>>>(Q, K, V, O);
}

// round 4
// speedup vs baseline: 8.8047x; 3.2752x over previous
#include <cuda_runtime.h>
#include <cstdint>

#define WINDOW 512
#define S_LEN  4096
#define BH     16
#define TQ     128
#define TK     64
#define DD     64
#define NTH    256
#define NWARP  8

// smem byte offsets (bf16 tiles, 128B rows, SW128 swizzle)
#define SM_QH 0
#define SM_QL 16384
#define SM_KH 32768
#define SM_KL 40960
#define SM_VH 49152
#define SM_VL 57344
#define SM_TOTAL 65536

#define SWZ(x) ((x) ^ (((x) >> 3) & 0x70))

static __device__ __forceinline__ uint32_t s2u(const void* p) {
    uint32_t a;
    asm("{ .reg .u64 t; cvta.to.shared.u64 t, %1; cvt.u32.u64 %0, t; }" : "=r"(a) : "l"(p));
    return a;
}
static __device__ __forceinline__ float ex2f_(float x) {
    float y; asm("ex2.approx.f32 %0,%1;" : "=f"(y) : "f"(x)); return y;
}
// pack two floats as bf16x2: low half = first arg, high half = second arg
static __device__ __forceinline__ uint32_t packbf(float lo, float hi) {
    uint32_t r;
    asm("cvt.rn.bf16x2.f32 %0, %1, %2;" : "=r"(r) : "f"(hi), "f"(lo));
    return r;
}
// hi/lo bf16 split of a float pair
static __device__ __forceinline__ void split2(float a, float b, uint32_t& h, uint32_t& l) {
    h = packbf(a, b);
    float ra = a - __uint_as_float(h << 16);
    float rb = b - __uint_as_float(h & 0xFFFF0000u);
    l = packbf(ra, rb);
}

static __device__ __forceinline__ void ldsm4(uint32_t r[4], uint32_t addr) {
    asm volatile("ldmatrix.sync.aligned.m8n8.x4.shared.b16 {%0,%1,%2,%3}, [%4];"
                 : "=r"(r[0]), "=r"(r[1]), "=r"(r[2]), "=r"(r[3]) : "r"(addr));
}
static __device__ __forceinline__ void ldsm4t(uint32_t r[4], uint32_t addr) {
    asm volatile("ldmatrix.sync.aligned.m8n8.x4.trans.shared.b16 {%0,%1,%2,%3}, [%4];"
                 : "=r"(r[0]), "=r"(r[1]), "=r"(r[2]), "=r"(r[3]) : "r"(addr));
}
static __device__ __forceinline__ void mma16816(float c[4], const uint32_t a[4],
                                                uint32_t b0, uint32_t b1) {
    asm volatile(
        "mma.sync.aligned.m16n8k16.row.col.f32.bf16.bf16.f32 "
        "{%0,%1,%2,%3}, {%4,%5,%6,%7}, {%8,%9}, {%0,%1,%2,%3};"
        : "+f"(c[0]), "+f"(c[1]), "+f"(c[2]), "+f"(c[3])
        : "r"(a[0]), "r"(a[1]), "r"(a[2]), "r"(a[3]), "r"(b0), "r"(b1));
}

// read 16 consecutive floats, scale, split to bf16 hi/lo, store 2x16B each
static __device__ __forceinline__ void store16split(const float4* g, char* sH, char* sL,
                                                    int rel, float scale) {
    float4 f[4];
    #pragma unroll
    for (int i = 0; i < 4; i++) f[i] = g[i];
    uint32_t h[8], l[8];
    #pragma unroll
    for (int i = 0; i < 4; i++) {
        split2(f[i].x * scale, f[i].y * scale, h[2 * i],     l[2 * i]);
        split2(f[i].z * scale, f[i].w * scale, h[2 * i + 1], l[2 * i + 1]);
    }
    *(uint4*)(sH + SWZ(rel))      = make_uint4(h[0], h[1], h[2], h[3]);
    *(uint4*)(sH + SWZ(rel + 16)) = make_uint4(h[4], h[5], h[6], h[7]);
    *(uint4*)(sL + SWZ(rel))      = make_uint4(l[0], l[1], l[2], l[3]);
    *(uint4*)(sL + SWZ(rel + 16)) = make_uint4(l[4], l[5], l[6], l[7]);
}

extern __shared__ __align__(1024) char smem[];

__global__ void __launch_bounds__(NTH, 1)
swa_mma_kernel(const float* __restrict__ Qp,
               const float* __restrict__ Kp,
               const float* __restrict__ Vp,
               float* __restrict__ Op) {
    const int tid  = threadIdx.x;
    const int lane = tid & 31;
    const int warp = tid >> 5;
    const int bh   = blockIdx.y;
    const int q0   = blockIdx.x * TQ;
    const size_t base = (size_t)bh * S_LEN * DD;
    const uint32_t sb = s2u(smem);

    // ---- stage Q (128x64) into smem as hi/lo bf16, pre-scaled to log2 domain ----
    {
        const float qs = 0.125f * 1.44269504088896340736f;
        const int trow = tid >> 2, q4 = tid & 3;
        #pragma unroll
        for (int half = 0; half < 2; half++) {
            const int row = trow + half * 64;
            const float4* g = (const float4*)(Qp + base + (size_t)(q0 + row) * DD + q4 * 16);
            store16split(g, smem + SM_QH, smem + SM_QL, row * 128 + q4 * 32, qs);
        }
    }

    // per-lane fragment address components
    const int g_   = lane >> 2;          // row within m8 group
    const int tig  = lane & 3;
    const int rowA = (warp << 4) + (lane & 15);
    const int cA16 = (lane >> 4) * 16;
    const int rkK  = (lane & 7) + ((lane >> 4) & 1) * 8;
    const int cK16 = ((lane >> 3) & 1) * 16;
    const int rkV  = (lane & 7) + ((lane >> 3) & 1) * 8;
    const int cV16 = ((lane >> 4) & 1) * 16;

    float o[8][4];
    #pragma unroll
    for (int i = 0; i < 8; i++)
        #pragma unroll
        for (int e = 0; e < 4; e++) o[i][e] = 0.0f;
    float l0 = 0.0f, l1 = 0.0f;

    const int qmin = q0 + (warp << 4);
    const int qmax = qmin + 15;
    const int kt0 = (q0 >= WINDOW - 1) ? ((q0 - WINDOW + 1) >> 6) : 0;
    const int kt1 = (q0 + TQ - 1) >> 6;

    for (int kt = kt0; kt <= kt1; kt++) {
        __syncthreads();   // previous tile fully consumed
        // ---- cooperative K/V tile load + bf16 split ----
        {
            const int trow = tid >> 2, q4 = tid & 3;
            const float4* kg = (const float4*)(Kp + base + (size_t)(kt * TK + trow) * DD + q4 * 16);
            store16split(kg, smem + SM_KH, smem + SM_KL, trow * 128 + q4 * 32, 1.0f);
            const float4* vg = (const float4*)(Vp + base + (size_t)(kt * TK + trow) * DD + q4 * 16);
            store16split(vg, smem + SM_VH, smem + SM_VL, trow * 128 + q4 * 32, 1.0f);
        }
        __syncthreads();

        // per-warp window skip (all lanes uniform)
        if (kt * TK > qmax || kt * TK + (TK - 1) < qmin - (WINDOW - 1)) continue;

        // ---- QK^T: S = (Qh+Ql)(Kh+Kl)^T, 3 combos ----
        float s[8][4];
        #pragma unroll
        for (int i = 0; i < 8; i++)
            #pragma unroll
            for (int e = 0; e < 4; e++) s[i][e] = 0.0f;

        #pragma unroll
        for (int kc = 0; kc < 4; kc++) {
            uint32_t aqh[4], aql[4];
            ldsm4(aqh, sb + SM_QH + SWZ(rowA * 128 + kc * 32 + cA16));
            ldsm4(aql, sb + SM_QL + SWZ(rowA * 128 + kc * 32 + cA16));
            #pragma unroll
            for (int pr = 0; pr < 4; pr++) {
                const uint32_t off = SWZ((pr * 16 + rkK) * 128 + kc * 32 + cK16);
                uint32_t bh_[4], bl_[4];
                ldsm4(bh_, sb + SM_KH + off);
                ldsm4(bl_, sb + SM_KL + off);
                mma16816(s[2 * pr],     aqh, bh_[0], bh_[1]);
                mma16816(s[2 * pr + 1], aqh, bh_[2], bh_[3]);
                mma16816(s[2 * pr],     aqh, bl_[0], bl_[1]);
                mma16816(s[2 * pr + 1], aqh, bl_[2], bl_[3]);
                mma16816(s[2 * pr],     aql, bh_[0], bh_[1]);
                mma16816(s[2 * pr + 1], aql, bh_[2], bh_[3]);
            }
        }

        // ---- softmax numerator + repack into PV A-fragments ----
        uint32_t pah[4][4], pal[4][4];
        const int qr0 = q0 + (warp << 4) + g_;   // row of c0/c1
        const int qr1 = qr0 + 8;                 // row of c2/c3
        const int jb  = kt * TK;
        #pragma unroll
        for (int nb = 0; nb < 8; nb++) {
            const int j0 = jb + nb * 8 + 2 * tig;
            const int j1 = j0 + 1;
            float p0 = (j0 <= qr0 && j0 + (WINDOW - 1) >= qr0) ? ex2f_(s[nb][0]) : 0.0f;
            float p1 = (j1 <= qr0 && j1 + (WINDOW - 1) >= qr0) ? ex2f_(s[nb][1]) : 0.0f;
            float p2 = (j0 <= qr1 && j0 + (WINDOW - 1) >= qr1) ? ex2f_(s[nb][2]) : 0.0f;
            float p3 = (j1 <= qr1 && j1 + (WINDOW - 1) >= qr1) ? ex2f_(s[nb][3]) : 0.0f;
            l0 += p0 + p1;
            l1 += p2 + p3;
            uint32_t h01, lo01, h23, lo23;
            split2(p0, p1, h01, lo01);
            split2(p2, p3, h23, lo23);
            const int kc2 = nb >> 1, sub = nb & 1;
            pah[kc2][sub * 2]     = h01;
            pah[kc2][sub * 2 + 1] = h23;
            pal[kc2][sub * 2]     = lo01;
            pal[kc2][sub * 2 + 1] = lo23;
        }

        // ---- PV: O += (Ph+Pl)(Vh+Vl), 3 combos ----
        #pragma unroll
        for (int kc2 = 0; kc2 < 4; kc2++) {
            #pragma unroll
            for (int pr = 0; pr < 4; pr++) {
                const uint32_t off = SWZ((kc2 * 16 + rkV) * 128 + pr * 32 + cV16);
                uint32_t vh_[4], vl_[4];
                ldsm4t(vh_, sb + SM_VH + off);
                ldsm4t(vl_, sb + SM_VL + off);
                mma16816(o[2 * pr],     pah[kc2], vh_[0], vh_[1]);
                mma16816(o[2 * pr + 1], pah[kc2], vh_[2], vh_[3]);
                mma16816(o[2 * pr],     pah[kc2], vl_[0], vl_[1]);
                mma16816(o[2 * pr + 1], pah[kc2], vl_[2], vl_[3]);
                mma16816(o[2 * pr],     pal[kc2], vh_[0], vh_[1]);
                mma16816(o[2 * pr + 1], pal[kc2], vh_[2], vh_[3]);
            }
        }
    }

    // ---- finalize: row sums across the 4 lanes of each group, normalize, store ----
    l0 += __shfl_xor_sync(0xffffffffu, l0, 1);
    l0 += __shfl_xor_sync(0xffffffffu, l0, 2);
    l1 += __shfl_xor_sync(0xffffffffu, l1, 1);
    l1 += __shfl_xor_sync(0xffffffffu, l1, 2);
    const float inv0 = 1.0f / l0;
    const float inv1 = 1.0f / l1;

    const int r0 = q0 + (warp << 4) + g_;
    const int r1 = r0 + 8;
    float* orow0 = Op + base + (size_t)r0 * DD;
    float* orow1 = Op + base + (size_t)r1 * DD;
    #pragma unroll
    for (int nb = 0; nb < 8; nb++) {
        const int c = nb * 8 + 2 * tig;
        *(float2*)(orow0 + c) = make_float2(o[nb][0] * inv0, o[nb][1] * inv0);
        *(float2*)(orow1 + c) = make_float2(o[nb][2] * inv1, o[nb][3] * inv1);
    }
}

extern "C" void kernel_launch(void* const* d_in, const int* in_sizes, int n_in,
                              void* d_out, int out_size) {
    const float* Q = (const float*)d_in[0];
    const float* K = (const float*)d_in[1];
    const float* V = (const float*)d_in[2];
    float* O = (float*)d_out;
    (void)in_sizes; (void)n_in; (void)out_size;

    cudaFuncSetAttribute(swa_mma_kernel, cudaFuncAttributeMaxDynamicSharedMemorySize, SM_TOTAL);
    dim3 grid(S_LEN / TQ, BH);   // (32, 16) = 512 blocks
    swa_mma_kernel<<<grid, NTH, SM_TOTAL>>>(Q, K, V, O);
}